// round 11
// baseline (speedup 1.0000x reference)
#include <cuda_runtime.h>
#include <cuda_bf16.h>
#include <cstdint>

// DeltaNet fused recurrent decode step.
//   s1  = bf16(exp(gate) * state) ; acc = k^T s1 ; delta = beta*(v - acc)
//   s2  = bf16(s1 + k (outer) delta) ; out = bf16(q^T s2)
// ALL buffers are float32 (harness upcasts the bf16 reference tensors; numpy
// has no bf16). bf16 rounding is emulated internally. Insertion order
// (q,k,v,beta,gate,state), in_sizes = element counts, out = float32.

static __device__ __forceinline__ float bf16r(float x) {
    return __bfloat162float(__float2bfloat16(x));
}

// ---------------- Fast path: DK = DV = 128 ----------------
__global__ void __launch_bounds__(128)
deltanet_f32_128(const float* __restrict__ q,
                 const float* __restrict__ k,
                 const float* __restrict__ v,
                 const float* __restrict__ beta,
                 const float* __restrict__ gate,
                 const float* __restrict__ state,
                 float* __restrict__ out)
{
    constexpr int D = 128;
    __shared__ __align__(16) __nv_bfloat16 s1sm[D * D];  // 32 KB decayed state (exact bf16)
    __shared__ float ksm[D];
    __shared__ float qsm[D];
    __shared__ __align__(16) float red[4][D];

    const int bh = blockIdx.x;
    const int t  = threadIdx.x;
    const int qt = t >> 5;      // dk quarter
    const int c  = t & 31;
    const int col = 4 * c;      // 4 dv columns per thread

    const float* st = state + (size_t)bh * (D * D);

    ksm[t] = __ldg(k + (size_t)bh * D + t);
    qsm[t] = __ldg(q + (size_t)bh * D + t);

    const float decay = expf(__ldg(gate + bh));
    const float betaf = __ldg(beta + bh);
    __syncthreads();

    // ---- Pass 1: s1 = bf16(decay*S) -> smem; acc = k^T s1 ----
    float acc0 = 0.f, acc1 = 0.f, acc2 = 0.f, acc3 = 0.f;
#pragma unroll 8
    for (int i = 0; i < 32; ++i) {
        const int dk = qt * 32 + i;
        // float4 streaming load: 402MB state touched exactly once
        const float4 f = __ldcs(reinterpret_cast<const float4*>(st + (size_t)dk * D + col));

        // bf16 round-to-nearest-even after decay (reference stores s1 as bf16)
        const __nv_bfloat16 b0 = __float2bfloat16(f.x * decay);
        const __nv_bfloat16 b1 = __float2bfloat16(f.y * decay);
        const __nv_bfloat16 b2 = __float2bfloat16(f.z * decay);
        const __nv_bfloat16 b3 = __float2bfloat16(f.w * decay);

        const __nv_bfloat162 p01 = __halves2bfloat162(b0, b1);
        const __nv_bfloat162 p23 = __halves2bfloat162(b2, b3);
        uint2 packed;
        packed.x = *reinterpret_cast<const uint32_t*>(&p01);
        packed.y = *reinterpret_cast<const uint32_t*>(&p23);
        *reinterpret_cast<uint2*>(s1sm + dk * D + col) = packed;

        const float kf = ksm[dk];
        acc0 += kf * __bfloat162float(b0);
        acc1 += kf * __bfloat162float(b1);
        acc2 += kf * __bfloat162float(b2);
        acc3 += kf * __bfloat162float(b3);
    }

    *reinterpret_cast<float4*>(&red[qt][col]) = make_float4(acc0, acc1, acc2, acc3);
    __syncthreads();

    float delta[4];
#pragma unroll
    for (int j = 0; j < 4; ++j) {
        const float a = red[0][col + j] + red[1][col + j] +
                        red[2][col + j] + red[3][col + j];
        const float vf = __ldg(v + (size_t)bh * D + col + j);
        delta[j] = betaf * (vf - a);
    }
    __syncthreads();   // red consumed before pass-2 overwrites it

    // ---- Pass 2: out = q^T bf16(s1 + k*delta), s1 from smem ----
    float o0 = 0.f, o1 = 0.f, o2 = 0.f, o3 = 0.f;
#pragma unroll 8
    for (int i = 0; i < 32; ++i) {
        const int dk = qt * 32 + i;
        const uint2 raw = *reinterpret_cast<const uint2*>(s1sm + dk * D + col);
        __nv_bfloat162 p0, p1;
        *reinterpret_cast<uint32_t*>(&p0) = raw.x;
        *reinterpret_cast<uint32_t*>(&p1) = raw.y;

        const float kf = ksm[dk];
        const float qf = qsm[dk];

        o0 += qf * bf16r(__bfloat162float(p0.x) + kf * delta[0]);
        o1 += qf * bf16r(__bfloat162float(p0.y) + kf * delta[1]);
        o2 += qf * bf16r(__bfloat162float(p1.x) + kf * delta[2]);
        o3 += qf * bf16r(__bfloat162float(p1.y) + kf * delta[3]);
    }

    *reinterpret_cast<float4*>(&red[qt][col]) = make_float4(o0, o1, o2, o3);
    __syncthreads();

    // Quarter 0 reduces and writes f32 output (bf16-rounded, matching reference)
    if (qt == 0) {
        float s[4];
#pragma unroll
        for (int j = 0; j < 4; ++j) {
            const float r = red[0][col + j] + red[1][col + j] +
                            red[2][col + j] + red[3][col + j];
            s[j] = bf16r(r);
        }
        *reinterpret_cast<float4*>(out + (size_t)bh * D + col) =
            make_float4(s[0], s[1], s[2], s[3]);
    }
}

// ---------------- Generic fallback: runtime DK, DV ----------------
__global__ void __launch_bounds__(128)
deltanet_f32_gen(const float* __restrict__ q,
                 const float* __restrict__ k,
                 const float* __restrict__ v,
                 const float* __restrict__ beta,
                 const float* __restrict__ gate,
                 const float* __restrict__ state,
                 float* __restrict__ out,
                 int DK, int DV)
{
    extern __shared__ float dyn[];   // ks[DK], qs[DK]
    float* ks = dyn;
    float* qs = dyn + DK;

    const int bh = blockIdx.x;
    const int t  = threadIdx.x;

    for (int i = t; i < DK; i += 128) {
        ks[i] = __ldg(k + (size_t)bh * DK + i);
        qs[i] = __ldg(q + (size_t)bh * DK + i);
    }
    __syncthreads();

    const float decay = expf(__ldg(gate + bh));
    const float betaf = __ldg(beta + bh);
    const float* S = state + (size_t)bh * DK * DV;

    for (int j = t; j < DV; j += 128) {
        float acc = 0.0f;
        for (int dk = 0; dk < DK; ++dk)
            acc += ks[dk] * bf16r(__ldg(S + (size_t)dk * DV + j) * decay);

        const float delta = betaf * (__ldg(v + (size_t)bh * DV + j) - acc);

        float o = 0.0f;
        for (int dk = 0; dk < DK; ++dk) {
            const float s1 = bf16r(__ldg(S + (size_t)dk * DV + j) * decay);
            o += qs[dk] * bf16r(s1 + ks[dk] * delta);
        }
        out[(size_t)bh * DV + j] = bf16r(o);
    }
}

extern "C" void kernel_launch(void* const* d_in, const int* in_sizes, int n_in,
                              void* d_out, int out_size)
{
    // Insertion order (q, k, v, beta, gate, state); in_sizes = element counts;
    // ALL buffers float32.
    const float* q     = (const float*)d_in[0];
    const float* k     = (const float*)d_in[1];
    const float* v     = (const float*)d_in[2];
    const float* beta  = (const float*)d_in[3];
    const float* gate  = (const float*)d_in[4];
    const float* state = (const float*)d_in[5];
    float* out = (float*)d_out;

    const long long BH = in_sizes[3];                 // |beta| = B*H
    const long long DK = (long long)in_sizes[0] / BH; // |q| / BH
    const long long DV = (long long)in_sizes[2] / BH; // |v| / BH

    if (DK == 128 && DV == 128) {
        deltanet_f32_128<<<(unsigned)BH, 128>>>(q, k, v, beta, gate, state, out);
    } else {
        const size_t shmem = (size_t)(2 * DK) * sizeof(float);
        deltanet_f32_gen<<<(unsigned)BH, 128, shmem>>>(
            q, k, v, beta, gate, state, out, (int)DK, (int)DV);
    }
}